// round 2
// baseline (speedup 1.0000x reference)
#include <cuda_runtime.h>
#include <math.h>

#define NP   128
#define DD   2048
#define NN   16384
#define NBLK 128
#define NTHR 256

// ---------------- scratch (no allocations allowed) ----------------
__device__ float    g_part[8*NN];     // split-K partials for P
__device__ float    g_P[NN];          // P = V G^T / n
__device__ float    g_S[NN];          // S = n P P^T
__device__ float    g_d[NN];          // dMsd
__device__ float    g_W[NN];          // out = W @ G
__device__ unsigned g_hist1[65536];
__device__ unsigned g_hist2[65536];
__device__ float    g_consts[2];      // inv2h, invh
__device__ unsigned g_sel[2];         // selected top16 key, remaining rank
__device__ volatile unsigned g_sense;
__device__ unsigned g_count;

// ---------------- shared memory union ----------------
struct SmemAll {
    union {
        struct { float4 As[32][17]; float4 Bs[32][17]; } a;             // GEMM tiles
        struct { unsigned csum[256]; unsigned bins[256]; unsigned sel[4]; } s; // radix scan
        struct { float krow[128]; float red[128]; float pacc[2][128]; } e;     // W rows
        struct { float Wb[8][128]; } f;                                  // final GEMM
    };
};

// ---------------- grid-wide barrier (sense-reversing, deterministic) ----------------
__device__ __forceinline__ void gbar(unsigned& lsense) {
    unsigned target = lsense ^ 1u;
    __syncthreads();
    if (threadIdx.x == 0) {
        __threadfence();
        if (atomicAdd(&g_count, 1u) == NBLK - 1u) {
            g_count = 0u;
            __threadfence();
            g_sense = target;
        } else {
            while (g_sense != target) { }
            __threadfence();
        }
    }
    __syncthreads();
    lsense = target;
}

// ---------------- 32x32 tile of A(row-major) dot B(row-major) over K slice ----------------
__device__ __forceinline__ void dot_tile(SmemAll* sm,
                                         const float* __restrict__ A,
                                         const float* __restrict__ B,
                                         float* __restrict__ C,
                                         int bx, int by, int kbase, int ksz, int K,
                                         float scale)
{
    int t  = threadIdx.x;
    int tx = t & 15, ty = t >> 4;
    int K4 = K >> 2;
    int q0base = kbase >> 2;
    const float4* A4 = (const float4*)A;
    const float4* B4 = (const float4*)B;
    int arow0 = by * 32, brow0 = bx * 32;

    float a00 = 0.f, a01 = 0.f, a10 = 0.f, a11 = 0.f;

    for (int c0 = 0; c0 < ksz; c0 += 64) {
        int q0 = q0base + (c0 >> 2);
        #pragma unroll
        for (int tt = 0; tt < 2; tt++) {
            int idx = t + tt * 256;
            int r = idx >> 4, q = idx & 15;
            sm->a.As[r][q] = A4[(arow0 + r) * K4 + q0 + q];
            sm->a.Bs[r][q] = B4[(brow0 + r) * K4 + q0 + q];
        }
        __syncthreads();
        #pragma unroll
        for (int q = 0; q < 16; q++) {
            float4 av0 = sm->a.As[2*ty  ][q];
            float4 av1 = sm->a.As[2*ty+1][q];
            float4 bv0 = sm->a.Bs[2*tx  ][q];
            float4 bv1 = sm->a.Bs[2*tx+1][q];
            a00 += av0.x*bv0.x + av0.y*bv0.y + av0.z*bv0.z + av0.w*bv0.w;
            a01 += av0.x*bv1.x + av0.y*bv1.y + av0.z*bv1.z + av0.w*bv1.w;
            a10 += av1.x*bv0.x + av1.y*bv0.y + av1.z*bv0.z + av1.w*bv0.w;
            a11 += av1.x*bv1.x + av1.y*bv1.y + av1.z*bv1.z + av1.w*bv1.w;
        }
        __syncthreads();
    }
    int r0 = arow0 + 2*ty, c0o = brow0 + 2*tx;
    C[ r0   *NP + c0o    ] = a00 * scale;
    C[ r0   *NP + c0o + 1] = a01 * scale;
    C[(r0+1)*NP + c0o    ] = a10 * scale;
    C[(r0+1)*NP + c0o + 1] = a11 * scale;
}

// ---------------- two-level 256x256 scan over a 65536-bin histogram ----------------
// Finds bin index containing 0-based rank k; writes sm->s.sel[2]=bin, sel[3]=rank-within-bin.
__device__ __forceinline__ void scan_select(SmemAll* sm, const unsigned* __restrict__ hist,
                                            unsigned k)
{
    int t = threadIdx.x;
    unsigned s = 0;
    #pragma unroll 8
    for (int i = 0; i < 256; i++) s += hist[t * 256 + i];
    sm->s.csum[t] = s;
    __syncthreads();
    if (t == 0) {
        unsigned cum = 0; int c = 0;
        for (; c < 255; c++) {
            unsigned h = sm->s.csum[c];
            if (cum + h > k) break;
            cum += h;
        }
        sm->s.sel[0] = (unsigned)c;
        sm->s.sel[1] = k - cum;
    }
    __syncthreads();
    int chunk = (int)sm->s.sel[0];
    unsigned kin = sm->s.sel[1];
    sm->s.bins[t] = hist[chunk * 256 + t];
    __syncthreads();
    if (t == 0) {
        unsigned cum = 0; int i = 0;
        for (; i < 255; i++) {
            unsigned h = sm->s.bins[i];
            if (cum + h > kin) break;
            cum += h;
        }
        sm->s.sel[2] = (unsigned)(chunk * 256 + i);
        sm->s.sel[3] = kin - cum;
    }
    __syncthreads();
}

__device__ __forceinline__ unsigned f2key(float d) {
    unsigned u = __float_as_uint(d);
    return (u & 0x80000000u) ? ~u : (u | 0x80000000u);
}

// ==================================================================
__global__ void __launch_bounds__(NTHR, 1)
stein_fused(const float* __restrict__ V, const float* __restrict__ G,
            float* __restrict__ out)
{
    __shared__ SmemAll sm;
    int b = blockIdx.x, t = threadIdx.x;
    int gid = b * NTHR + t;
    unsigned lsense = g_sense;   // snapshot before any barrier (replay-safe)

    // ---- Phase A: P partials (split-K x8): g_part[z] = V_tile . G_tile ----
    {
        int tile = b & 15, z = b >> 4;
        dot_tile(&sm, V, G, g_part + z * NN, tile & 3, tile >> 2, z * 256, 256, DD, 1.0f);
    }
    gbar(lsense);

    // ---- Phase B: reduce partials -> P = V G^T / n ----
    if (gid < NN) {
        float s = 0.f;
        #pragma unroll
        for (int z = 0; z < 8; z++) s += g_part[z * NN + gid];
        g_P[gid] = s * (1.0f / 128.0f);
    }
    gbar(lsense);

    // ---- Phase C: S = n P P^T (blocks 0..15); others zero histograms ----
    if (b < 16) {
        dot_tile(&sm, g_P, g_P, g_S, b & 3, b >> 2, 0, 128, 128, 128.0f);
    } else {
        for (int idx = (b - 16) * NTHR + t; idx < 131072; idx += 112 * NTHR) {
            if (idx < 65536) g_hist1[idx] = 0u;
            else             g_hist2[idx - 65536] = 0u;
        }
    }
    gbar(lsense);

    // ---- Phase D1: dMsd + top-16-bit histogram ----
    if (gid < NN) {
        int i = gid >> 7, j = gid & 127;
        float d = g_S[i*NP + i] + g_S[j*NP + j] - g_S[i*NP + j] - g_S[j*NP + i];
        g_d[gid] = d;
        atomicAdd(&g_hist1[f2key(d) >> 16], 1u);
    }
    gbar(lsense);

    // ---- Phase D2: select top16 bucket containing rank 8192 ----
    if (b == 0) {
        scan_select(&sm, g_hist1, 8192u);
        if (t == 0) { g_sel[0] = sm.s.sel[2]; g_sel[1] = sm.s.sel[3]; }
    }
    gbar(lsense);

    // ---- Phase D3: low-16-bit histogram among matching elements ----
    {
        unsigned sel = g_sel[0];
        if (gid < NN) {
            unsigned key = f2key(g_d[gid]);
            if ((key >> 16) == sel) atomicAdd(&g_hist2[key & 0xFFFFu], 1u);
        }
    }
    gbar(lsense);

    // ---- Phase D4: exact median key -> h ----
    if (b == 0) {
        scan_select(&sm, g_hist2, g_sel[1]);
        if (t == 0) {
            unsigned key = (g_sel[0] << 16) | sm.s.sel[2];
            unsigned u = (key & 0x80000000u) ? (key ^ 0x80000000u) : ~key;
            float med = __uint_as_float(u);
            float h = (med * med) / 6.9314718f;   // ln(128)
            g_consts[0] = 0.5f / h;
            g_consts[1] = 1.0f / h;
        }
    }
    gbar(lsense);

    // ---- Phase E: W[i,:] = kern[i,:] + invh*(kern[i,:]@P - rs0*P[i,:]) (block b -> row b) ----
    {
        int i = b;
        float inv2h = g_consts[0], invh = g_consts[1];
        if (t < 128) {
            float d = g_d[i*NP + t];
            float kv = expf(-d * inv2h);
            sm.e.krow[t] = kv;
            sm.e.red[t]  = kv;
        }
        __syncthreads();
        for (int s = 64; s > 0; s >>= 1) {
            if (t < s) sm.e.red[t] += sm.e.red[t + s];
            __syncthreads();
        }
        float rs0 = sm.e.red[0];

        int c = t & 127, half = t >> 7;
        float acc = 0.f;
        int j0 = half * 64;
        #pragma unroll 4
        for (int j = j0; j < j0 + 64; j++) acc += sm.e.krow[j] * g_P[j*NP + c];
        sm.e.pacc[half][c] = acc;
        __syncthreads();
        if (t < 128) {
            float a = sm.e.pacc[0][t] + sm.e.pacc[1][t];
            g_W[i*NP + t] = sm.e.krow[t] + invh * (a - rs0 * g_P[i*NP + t]);
        }
    }
    gbar(lsense);

    // ---- Phase F: out = W @ G  (block: 8 rows x 256 cols) ----
    {
        int rg = b >> 3, cg = b & 7;
        int r0 = rg * 8, c = cg * 256 + t;
        for (int idx = t; idx < 1024; idx += 256)
            sm.f.Wb[idx >> 7][idx & 127] = g_W[(r0 + (idx >> 7)) * NP + (idx & 127)];
        __syncthreads();

        float acc[8];
        #pragma unroll
        for (int r = 0; r < 8; r++) acc[r] = 0.f;

        #pragma unroll 4
        for (int j = 0; j < 128; j++) {
            float gv = G[j * DD + c];
            #pragma unroll
            for (int r = 0; r < 8; r++) acc[r] += sm.f.Wb[r][j] * gv;
        }
        #pragma unroll
        for (int r = 0; r < 8; r++) out[(r0 + r) * DD + c] = acc[r];
    }
}

extern "C" void kernel_launch(void* const* d_in, const int* in_sizes, int n_in,
                              void* d_out, int out_size)
{
    const float* var  = (const float*)d_in[0];
    const float* grad = (const float*)d_in[1];
    float* out = (float*)d_out;
    stein_fused<<<NBLK, NTHR>>>(var, grad, out);
}

// round 3
// speedup vs baseline: 1.7746x; 1.7746x over previous
#include <cuda_runtime.h>
#include <math.h>

#define NP   128
#define DD   2048
#define NN   16384
#define NBLK 128
#define NTHR 256

// ---------------- scratch (no allocations allowed) ----------------
__device__ float    g_part[8*NN];     // split-K partials for P
__device__ float    g_P[NN];          // P = V G^T / n
__device__ float    g_S[NN];          // S = n P P^T
__device__ float    g_W[NN];          // out = W @ G
__device__ float    g_consts[2];      // inv2h, invh
__device__ unsigned g_sense;
__device__ unsigned g_count;

// ---------------- shared memory union ----------------
struct SmemAll {
    union {
        struct { float4 As[32][17]; float4 Bs[32][17]; } a;               // GEMM tiles
        struct { float sdiag[128]; unsigned hist[256]; unsigned wsum[8];
                 unsigned sel[2]; } m;                                     // median
        struct { float sdiag[128]; float krow[128]; float red[128];
                 float pacc[2][128]; } e;                                  // W rows
        struct { float Wb[8][128]; } f;                                    // final GEMM
    };
};

// ---------------- acquire/release helpers ----------------
__device__ __forceinline__ unsigned ld_acq(unsigned* p) {
    unsigned v;
    asm volatile("ld.acquire.gpu.u32 %0, [%1];" : "=r"(v) : "l"(p) : "memory");
    return v;
}
__device__ __forceinline__ void st_rel(unsigned* p, unsigned v) {
    asm volatile("st.release.gpu.u32 [%0], %1;" :: "l"(p), "r"(v) : "memory");
}

// ---------------- grid-wide barrier (sense-reversing, deterministic) ----------------
__device__ __forceinline__ void gbar(unsigned& lsense) {
    unsigned target = lsense ^ 1u;
    __syncthreads();
    if (threadIdx.x == 0) {
        __threadfence();                       // release all prior writes
        if (atomicAdd(&g_count, 1u) == NBLK - 1u) {
            g_count = 0u;                      // ordered before release store
            st_rel(&g_sense, target);
        } else {
            while (ld_acq(&g_sense) != target) { }
        }
    }
    __syncthreads();
    lsense = target;
}

// ---------------- 32x32 tile of A(row-major) dot B(row-major) over K slice ----------------
__device__ __forceinline__ void dot_tile(SmemAll* sm,
                                         const float* __restrict__ A,
                                         const float* __restrict__ B,
                                         float* __restrict__ C,
                                         int bx, int by, int kbase, int ksz, int K,
                                         float scale)
{
    int t  = threadIdx.x;
    int tx = t & 15, ty = t >> 4;
    int K4 = K >> 2;
    int q0base = kbase >> 2;
    const float4* A4 = (const float4*)A;
    const float4* B4 = (const float4*)B;
    int arow0 = by * 32, brow0 = bx * 32;

    float a00 = 0.f, a01 = 0.f, a10 = 0.f, a11 = 0.f;

    for (int c0 = 0; c0 < ksz; c0 += 64) {
        int q0 = q0base + (c0 >> 2);
        #pragma unroll
        for (int tt = 0; tt < 2; tt++) {
            int idx = t + tt * 256;
            int r = idx >> 4, q = idx & 15;
            sm->a.As[r][q] = A4[(arow0 + r) * K4 + q0 + q];
            sm->a.Bs[r][q] = B4[(brow0 + r) * K4 + q0 + q];
        }
        __syncthreads();
        #pragma unroll
        for (int q = 0; q < 16; q++) {
            float4 av0 = sm->a.As[2*ty  ][q];
            float4 av1 = sm->a.As[2*ty+1][q];
            float4 bv0 = sm->a.Bs[2*tx  ][q];
            float4 bv1 = sm->a.Bs[2*tx+1][q];
            a00 += av0.x*bv0.x + av0.y*bv0.y + av0.z*bv0.z + av0.w*bv0.w;
            a01 += av0.x*bv1.x + av0.y*bv1.y + av0.z*bv1.z + av0.w*bv1.w;
            a10 += av1.x*bv0.x + av1.y*bv0.y + av1.z*bv0.z + av1.w*bv0.w;
            a11 += av1.x*bv1.x + av1.y*bv1.y + av1.z*bv1.z + av1.w*bv1.w;
        }
        __syncthreads();
    }
    int r0 = arow0 + 2*ty, c0o = brow0 + 2*tx;
    C[ r0   *NP + c0o    ] = a00 * scale;
    C[ r0   *NP + c0o + 1] = a01 * scale;
    C[(r0+1)*NP + c0o    ] = a10 * scale;
    C[(r0+1)*NP + c0o + 1] = a11 * scale;
}

__device__ __forceinline__ unsigned f2key(float d) {
    unsigned u = __float_as_uint(d);
    return (u & 0x80000000u) ? ~u : (u | 0x80000000u);
}

// ==================================================================
__global__ void __launch_bounds__(NTHR, 1)
stein_fused(const float* __restrict__ V, const float* __restrict__ G,
            float* __restrict__ out)
{
    __shared__ SmemAll sm;
    int b = blockIdx.x, t = threadIdx.x;
    int gid = b * NTHR + t;
    unsigned lsense = g_sense;   // snapshot before any barrier (replay-safe)

    // ---- Phase A: P partials (split-K x8) ----
    {
        int tile = b & 15, z = b >> 4;
        dot_tile(&sm, V, G, g_part + z * NN, tile & 3, tile >> 2, z * 256, 256, DD, 1.0f);
    }
    gbar(lsense);

    // ---- Phase B: reduce partials -> P = V G^T / n ----
    if (gid < NN) {
        float s = 0.f;
        #pragma unroll
        for (int z = 0; z < 8; z++) s += g_part[z * NN + gid];
        g_P[gid] = s * (1.0f / 128.0f);
    }
    gbar(lsense);

    // ---- Phase C: S = n P P^T (blocks 0..15) ----
    if (b < 16) {
        dot_tile(&sm, g_P, g_P, g_S, b & 3, b >> 2, 0, 128, 128, 128.0f);
    }
    gbar(lsense);

    // ---- Phase M: median of dMsd, block 0 only ----
    if (b == 0) {
        int lane = t & 31, wid = t >> 5;

        // diag of S into smem
        if (t < 128) sm.m.sdiag[t] = g_S[t * NP + t];
        __syncthreads();

        // compute 64 keys/thread into registers
        unsigned keys[64];
        int base = t * 64;
        int i = base >> 7;                 // fixed per thread (64 | 128 stride)
        int j0 = base & 127;
        float sdi = sm.m.sdiag[i];
        #pragma unroll
        for (int e = 0; e < 64; e++) {
            int j = j0 + e;
            float d = sdi + sm.m.sdiag[j] - g_S[i*NP + j] - g_S[j*NP + i];
            keys[e] = f2key(d);
        }

        unsigned hi_mask = 0u, hi_val = 0u;
        unsigned krank = 8192u;            // 0-based median rank (nearest of 16383/2)

        for (int p = 0; p < 4; p++) {
            int shift = 24 - 8 * p;
            sm.m.hist[t] = 0u;
            __syncthreads();

            // warp-aggregated histogram
            #pragma unroll
            for (int e = 0; e < 64; e++) {
                unsigned key = keys[e];
                bool ok = (key & hi_mask) == hi_val;
                unsigned bin = ok ? ((key >> shift) & 255u) : 0xFFFFFFFFu;
                unsigned m = __match_any_sync(0xFFFFFFFFu, bin);
                if (ok && ((int)(__ffs(m) - 1) == lane))
                    atomicAdd(&sm.m.hist[bin], (unsigned)__popc(m));
            }
            __syncthreads();

            // parallel scan over 256 bins
            unsigned v = sm.m.hist[t];
            unsigned incl = v;
            #pragma unroll
            for (int off = 1; off < 32; off <<= 1) {
                unsigned nv = __shfl_up_sync(0xFFFFFFFFu, incl, off);
                if (lane >= off) incl += nv;
            }
            if (lane == 31) sm.m.wsum[wid] = incl;
            __syncthreads();
            if (t < 8) {
                unsigned w = sm.m.wsum[t];
                unsigned in2 = w;
                #pragma unroll
                for (int off = 1; off < 8; off <<= 1) {
                    unsigned nv = __shfl_up_sync(0xFFu, in2, off);
                    if (t >= off) in2 += nv;
                }
                sm.m.wsum[t] = in2 - w;    // exclusive warp prefix
            }
            __syncthreads();
            unsigned excl = incl - v + sm.m.wsum[wid];
            if (excl <= krank && krank < excl + v) {
                sm.m.sel[0] = (unsigned)t;
                sm.m.sel[1] = krank - excl;
            }
            __syncthreads();
            unsigned bsel = sm.m.sel[0];
            krank = sm.m.sel[1];
            hi_mask |= (0xFFu << shift);
            hi_val  |= (bsel  << shift);
            __syncthreads();
        }

        if (t == 0) {
            unsigned key = hi_val;
            unsigned u = (key & 0x80000000u) ? (key ^ 0x80000000u) : ~key;
            float med = __uint_as_float(u);
            float h = (med * med) / 6.9314718f;   // ln(128)
            g_consts[0] = 0.5f / h;
            g_consts[1] = 1.0f / h;
        }
    }
    gbar(lsense);

    // ---- Phase E: W[i,:] = kern[i,:] + invh*(kern[i,:]@P - rs*P[i,:]) ----
    {
        int i = b;
        if (t < 128) sm.e.sdiag[t] = g_S[t * NP + t];
        __syncthreads();
        float inv2h = g_consts[0], invh = g_consts[1];
        if (t < 128) {
            float d = sm.e.sdiag[i] + sm.e.sdiag[t] - g_S[i*NP + t] - g_S[t*NP + i];
            float kv = expf(-d * inv2h);
            sm.e.krow[t] = kv;
            sm.e.red[t]  = kv;
        }
        __syncthreads();
        for (int s = 64; s > 0; s >>= 1) {
            if (t < s) sm.e.red[t] += sm.e.red[t + s];
            __syncthreads();
        }
        float rs0 = sm.e.red[0];

        int c = t & 127, half = t >> 7;
        float acc = 0.f;
        int j0 = half * 64;
        #pragma unroll 8
        for (int j = j0; j < j0 + 64; j++) acc += sm.e.krow[j] * g_P[j*NP + c];
        sm.e.pacc[half][c] = acc;
        __syncthreads();
        if (t < 128) {
            float a = sm.e.pacc[0][t] + sm.e.pacc[1][t];
            g_W[i*NP + t] = sm.e.krow[t] + invh * (a - rs0 * g_P[i*NP + t]);
        }
    }
    gbar(lsense);

    // ---- Phase F: out = W @ G  (block: 8 rows x 256 cols) ----
    {
        int rg = b >> 3, cg = b & 7;
        int r0 = rg * 8, c = cg * 256 + t;
        for (int idx = t; idx < 1024; idx += 256)
            sm.f.Wb[idx >> 7][idx & 127] = g_W[(r0 + (idx >> 7)) * NP + (idx & 127)];
        __syncthreads();

        float acc[8];
        #pragma unroll
        for (int r = 0; r < 8; r++) acc[r] = 0.f;

        #pragma unroll 8
        for (int j = 0; j < 128; j++) {
            float gv = G[j * DD + c];
            #pragma unroll
            for (int r = 0; r < 8; r++) acc[r] += sm.f.Wb[r][j] * gv;
        }
        #pragma unroll
        for (int r = 0; r < 8; r++) out[(r0 + r) * DD + c] = acc[r];
    }
}

extern "C" void kernel_launch(void* const* d_in, const int* in_sizes, int n_in,
                              void* d_out, int out_size)
{
    const float* var  = (const float*)d_in[0];
    const float* grad = (const float*)d_in[1];
    float* out = (float*)d_out;
    stein_fused<<<NBLK, NTHR>>>(var, grad, out);
}